// round 4
// baseline (speedup 1.0000x reference)
#include <cuda_runtime.h>
#include <math.h>

// Problem constants
#define NB    4
#define NC    17
#define NH    128
#define NW    128
#define HWSZ  (NH*NW)
#define NPC   51
#define NWID  128
#define NSTEP 48
#define ALIVE_IDX 3
#define ALIVE_THR 0.1f

#define CHW   (NC*HWSZ)
#define BCHW  (NB*CHW)
#define FINAL_ELEMS (NB*4*HWSZ)
#define NBLK  256

typedef unsigned long long ull;

// f32x2 packed-pair helpers (Blackwell FFMA2 path)
#define F2FMA(d, a, b, c) asm("fma.rn.f32x2 %0, %1, %2, %3;" : "=l"(d) : "l"(a), "l"(b), "l"(c))
#define F2MUL2(d, a, b)   asm("mul.rn.f32x2 %0, %1, %2;"     : "=l"(d) : "l"(a), "l"(b))
#define F2ADD(d, a, b)    asm("add.rn.f32x2 %0, %1, %2;"     : "=l"(d) : "l"(a), "l"(b))
#define PK2(d, lo, hi)    asm("mov.b64 %0, {%1, %2};" : "=l"(d) : "f"(lo), "f"(hi))
#define UPK2(lo, hi, s)   asm("mov.b64 {%0, %1}, %2;" : "=f"(lo), "=f"(hi) : "l"(s))

// Scratch (static device globals; no allocation allowed)
__device__ float         g_alive[NB * HWSZ];       // unmasked new alive channel
__device__ unsigned char g_amask[NB * HWSZ];       // per-pixel alive map (post-mask)
__device__ unsigned      g_count;                  // barrier arrival counter
__device__ volatile unsigned g_sense;              // barrier sense

__device__ __forceinline__ float ldz(const float* __restrict__ ch, int y, int x) {
    if (y < 0 || y >= NH || x < 0 || x >= NW) return 0.0f;
    return __ldg(ch + y * NW + x);
}

// Grid barrier: all NBLK blocks are co-resident by construction (256 blocks,
// 128 thr, occ>=2 on 148 SMs).
__device__ __forceinline__ void grid_barrier(unsigned target) {
    __syncthreads();
    if (threadIdx.x == 0) {
        __threadfence();
        if (atomicAdd(&g_count, 1u) == NBLK - 1u) {
            g_count = 0u;
            __threadfence();
            g_sense = target;
        } else {
            while (g_sense != target) __nanosleep(32);
            __threadfence();
        }
    }
    __syncthreads();
}

// Dynamic smem layout (ull units)
#define S_W1  0
#define S_W2  (128*52)
#define S_B1  (S_W2 + 128*18)
#define S_B2  (S_B1 + 128)
#define SMEM_ULLS (S_B2 + 18)
#define SMEM_BYTES (SMEM_ULLS * 8)

__global__ __launch_bounds__(128, 2)
void nca_persistent(const float* __restrict__ init_state,
                    const float* __restrict__ rnd_all,
                    const float* __restrict__ W1, const float* __restrict__ b1,
                    const float* __restrict__ W2, const float* __restrict__ b2,
                    float* __restrict__ dev_path,   // [48,B,C,H,W]
                    float* __restrict__ final_out)  // [B,4,H,W]
{
    extern __shared__ ull smem[];
    const int tid = threadIdx.x;

    // ---- load duplicated weights once ----
    for (int i = tid; i < 128 * 52; i += 128) {
        int o = i / 52, c = i - o * 52;
        float w = (c < NPC) ? W1[o * NPC + c] : 0.0f;
        ull d; PK2(d, w, w); smem[S_W1 + i] = d;
    }
    for (int i = tid; i < 128 * 18; i += 128) {
        int o = i / 18, j = i - o * 18;
        float w = (j < NC) ? W2[j * NWID + o] : 0.0f;
        ull d; PK2(d, w, w); smem[S_W2 + i] = d;
    }
    { float w = b1[tid]; ull d; PK2(d, w, w); smem[S_B1 + tid] = d; }
    if (tid < 18) { float w = (tid < NC) ? b2[tid] : 0.0f; ull d; PK2(d, w, w); smem[S_B2 + tid] = d; }

    int bias_ok = (b1[tid] <= 0.0f);
    if (tid < NC) bias_ok = bias_ok && (b2[tid] == 0.0f);
    const int allz = __syncthreads_and(bias_ok);

    // ---- geometry: block bid owns spatial region bid (16x4); its 4 warps
    //      handle the 4 batches of that region (load balance: the active blob
    //      is a contiguous bid band -> spread over distinct SMs). ----
    const int bid = blockIdx.x;          // 0..255 = spatial region
    const int rx  = bid & 7;             // region col (16 px wide)
    const int ry  = bid >> 3;            // region row (4 px tall)
    const int b   = tid >> 5;            // warp id = batch
    const int lane = tid & 31;
    const int pr  = lane & 7;            // pair col within region
    const int lyr = lane >> 3;           // row within region (0..3)
    const int bx0 = rx * 16;
    const int x0  = bx0 + pr * 2;
    const int y   = ry * 4 + lyr;
    const int pix = y * NW + x0;

    const ull* w1base = smem + S_W1;
    const ull* w2base = smem + S_W2;
    const ull* b1r    = smem + S_B1;

    unsigned bsense = 0;
    const float* cur = init_state;

    #pragma unroll 1
    for (int t = 0; t < NSTEP; t++) {
        float* dst  = dev_path + (size_t)t * BCHW;
        float* dout = dst + b * CHW + pix;
        float* gal  = g_alive + b * HWSZ + pix;

        // ================= PHASE A: step compute =================
        bool skipped = false;
        if (t > 0 && allz) {
            // check 18x6 alive-map halo of this warp's 16x4 region
            const int hx0 = bx0 - 1, hy0 = ry * 4 - 1;
            unsigned v = 0;
            #pragma unroll
            for (int i = lane; i < 108; i += 32) {
                int hx = hx0 + (i % 18);
                int hy = hy0 + (i / 18);
                if (hx >= 0 && hx < NW && hy >= 0 && hy < NH)
                    v |= __ldcg(&g_amask[b * HWSZ + hy * NW + hx]);
            }
            skipped = !__any_sync(0xFFFFFFFFu, v != 0);
        }

        if (skipped) {
            #pragma unroll
            for (int c = 0; c < NC; c++)
                *reinterpret_cast<ull*>(dout + c * HWSZ) = 0ULL;
            *reinterpret_cast<ull*>(gal) = 0ULL;
        } else {
            // ---- conv loads: 3x4 patch per channel ----
            ull p2[52];
            unsigned nz = 0u;
            const bool interior = (x0 >= 1) && (x0 + 2 < NW) && (y >= 1) && (y + 1 < NH);

            #pragma unroll
            for (int c = 0; c < NC; c++) {
                const float* ch = cur + (b * NC + c) * HWSZ + pix;
                float r0[4], r1[4], r2[4];
                if (interior) {
                    r0[0]=__ldg(ch-NW-1); r0[1]=__ldg(ch-NW); r0[2]=__ldg(ch-NW+1); r0[3]=__ldg(ch-NW+2);
                    r1[0]=__ldg(ch-1);    r1[1]=__ldg(ch);    r1[2]=__ldg(ch+1);    r1[3]=__ldg(ch+2);
                    r2[0]=__ldg(ch+NW-1); r2[1]=__ldg(ch+NW); r2[2]=__ldg(ch+NW+1); r2[3]=__ldg(ch+NW+2);
                } else {
                    const float* chb = cur + (b * NC + c) * HWSZ;
                    r0[0]=ldz(chb,y-1,x0-1); r0[1]=ldz(chb,y-1,x0); r0[2]=ldz(chb,y-1,x0+1); r0[3]=ldz(chb,y-1,x0+2);
                    r1[0]=ldz(chb,y  ,x0-1); r1[1]=ldz(chb,y  ,x0); r1[2]=ldz(chb,y  ,x0+1); r1[3]=ldz(chb,y  ,x0+2);
                    r2[0]=ldz(chb,y+1,x0-1); r2[1]=ldz(chb,y+1,x0); r2[2]=ldz(chb,y+1,x0+1); r2[3]=ldz(chb,y+1,x0+2);
                }
                nz |= __float_as_uint(r0[0]) | __float_as_uint(r0[1]) | __float_as_uint(r0[2]) | __float_as_uint(r0[3]);
                nz |= __float_as_uint(r1[0]) | __float_as_uint(r1[1]) | __float_as_uint(r1[2]) | __float_as_uint(r1[3]);
                nz |= __float_as_uint(r2[0]) | __float_as_uint(r2[1]) | __float_as_uint(r2[2]) | __float_as_uint(r2[3]);

                float gxA = ((r0[2]-r0[0]) + 2.0f*(r1[2]-r1[0]) + (r2[2]-r2[0])) * 0.125f;
                float gxB = ((r0[3]-r0[1]) + 2.0f*(r1[3]-r1[1]) + (r2[3]-r2[1])) * 0.125f;
                float gyA = ((r2[0]-r0[0]) + 2.0f*(r2[1]-r0[1]) + (r2[2]-r0[2])) * 0.125f;
                float gyB = ((r2[1]-r0[1]) + 2.0f*(r2[2]-r0[2]) + (r2[3]-r0[3])) * 0.125f;

                ull d;
                PK2(d, r1[1], r1[2]); p2[c]      = d;
                PK2(d, gxA,   gxB  ); p2[17 + c] = d;
                PK2(d, gyA,   gyB  ); p2[34 + c] = d;
            }
            p2[51] = 0ULL;

            const bool empty = allz && (nz == 0u);
            if (__all_sync(0xFFFFFFFFu, empty)) {
                skipped = true;  // provably zero output; phase B can skip too
                #pragma unroll
                for (int c = 0; c < NC; c++)
                    *reinterpret_cast<ull*>(dout + c * HWSZ) = 0ULL;
                *reinterpret_cast<ull*>(gal) = 0ULL;
            } else {
                // rotation
                {
                    float angA, angB; UPK2(angA, angB, p2[16]);
                    float saA, caA, saB, caB;
                    sincosf(angA, &saA, &caA);
                    sincosf(angB, &saB, &caB);
                    ull ca2, sa2, nsa2;
                    PK2(ca2, caA, caB); PK2(sa2, saA, saB); PK2(nsa2, -saA, -saB);
                    #pragma unroll
                    for (int c = 0; c < NC; c++) {
                        ull gx2 = p2[17 + c], gy2 = p2[34 + c], u;
                        F2MUL2(u, ca2, gx2); F2FMA(u, sa2, gy2, u);  p2[17 + c] = u;
                        F2MUL2(u, ca2, gy2); F2FMA(u, nsa2, gx2, u); p2[34 + c] = u;
                    }
                }

                // MLP
                ull dx2[18];
                #pragma unroll
                for (int j = 0; j < 18; j++) dx2[j] = smem[S_B2 + j];

                const ull* w1r = w1base;
                const ull* w2r = w2base;
                #pragma unroll 2
                for (int o = 0; o < NWID; o++) {
                    ull acc0 = b1r[o];
                    ull acc1 = 0ULL;
                    const ulonglong2* r = reinterpret_cast<const ulonglong2*>(w1r);
                    #pragma unroll
                    for (int q = 0; q < 26; q++) {
                        ulonglong2 wv = r[q];
                        F2FMA(acc0, wv.x, p2[2*q],     acc0);
                        F2FMA(acc1, wv.y, p2[2*q + 1], acc1);
                    }
                    ull hs; F2ADD(hs, acc0, acc1);
                    float hA, hB; UPK2(hA, hB, hs);
                    hA = fmaxf(hA, 0.0f); hB = fmaxf(hB, 0.0f);
                    ull h2; PK2(h2, hA, hB);

                    const ulonglong2* r2 = reinterpret_cast<const ulonglong2*>(w2r);
                    #pragma unroll
                    for (int q = 0; q < 9; q++) {
                        ulonglong2 wv = r2[q];
                        F2FMA(dx2[2*q],     wv.x, h2, dx2[2*q]);
                        F2FMA(dx2[2*q + 1], wv.y, h2, dx2[2*q + 1]);
                    }
                    w1r += 52; w2r += 18;
                }

                // stochastic update
                const float2 rr = *reinterpret_cast<const float2*>(
                    rnd_all + ((size_t)t * NB + b) * HWSZ + pix);
                float mA = (rr.x < 0.5f) ? 1.0f : 0.0f;
                float mB = (rr.y < 0.5f) ? 1.0f : 0.0f;
                ull m2; PK2(m2, mA, mB);

                #pragma unroll
                for (int c = 0; c < NC; c++) {
                    ull nv; F2FMA(nv, dx2[c], m2, p2[c]);
                    *reinterpret_cast<ull*>(dout + c * HWSZ) = nv;
                    if (c == ALIVE_IDX) *reinterpret_cast<ull*>(gal) = nv;
                }
            }
        }

        bsense ^= 1u; grid_barrier(bsense);

        // ================= PHASE B: alive masking =================
        const bool last = (t == NSTEP - 1);

        if (!skipped) {
            // combined 3x4 maxpool patches for the pixel pair
            float mo[4] = {-1e30f,-1e30f,-1e30f,-1e30f};
            float mn[4] = {-1e30f,-1e30f,-1e30f,-1e30f};
            const float* oa = cur + (b * NC + ALIVE_IDX) * HWSZ;
            const unsigned naoff = b * HWSZ;
            #pragma unroll
            for (int dy = -1; dy <= 1; dy++) {
                int yy = y + dy;
                if (yy < 0 || yy >= NH) continue;
                #pragma unroll
                for (int dxx = -1; dxx <= 2; dxx++) {
                    int xx = x0 + dxx;
                    if (xx < 0 || xx >= NW) continue;
                    int idx = yy * NW + xx;
                    float ov = __ldg(oa + idx);
                    float nv = __ldcg(&g_alive[naoff + idx]);
                    mo[dxx + 1] = fmaxf(mo[dxx + 1], ov);
                    mn[dxx + 1] = fmaxf(mn[dxx + 1], nv);
                }
            }
            float moA = fmaxf(fmaxf(mo[0], mo[1]), mo[2]);
            float moB = fmaxf(fmaxf(mo[1], mo[2]), mo[3]);
            float mnA = fmaxf(fmaxf(mn[0], mn[1]), mn[2]);
            float mnB = fmaxf(fmaxf(mn[1], mn[2]), mn[3]);
            const bool aliveA = (moA > ALIVE_THR) && (mnA > ALIVE_THR);
            const bool aliveB = (moB > ALIVE_THR) && (mnB > ALIVE_THR);

            // zero dead pixels (alive pixels already hold correct values)
            if (!aliveA && !aliveB) {
                #pragma unroll
                for (int c = 0; c < NC; c++)
                    *reinterpret_cast<ull*>(dout + c * HWSZ) = 0ULL;
            } else if (!aliveA) {
                #pragma unroll
                for (int c = 0; c < NC; c++) dout[c * HWSZ] = 0.0f;
            } else if (!aliveB) {
                #pragma unroll
                for (int c = 0; c < NC; c++) dout[c * HWSZ + 1] = 0.0f;
            }
            uchar2 am; am.x = aliveA ? 1 : 0; am.y = aliveB ? 1 : 0;
            *reinterpret_cast<uchar2*>(&g_amask[b * HWSZ + pix]) = am;

            if (last) {
                #pragma unroll
                for (int c = 0; c < 4; c++) {
                    float vA = aliveA ? dout[c * HWSZ]     : 0.0f;
                    float vB = aliveB ? dout[c * HWSZ + 1] : 0.0f;
                    float2 fv; fv.x = vA; fv.y = vB;
                    *reinterpret_cast<float2*>(final_out + (b * 4 + c) * HWSZ + pix) = fv;
                }
            }
        } else if (last) {
            #pragma unroll
            for (int c = 0; c < 4; c++)
                *reinterpret_cast<ull*>(final_out + (b * 4 + c) * HWSZ + pix) = 0ULL;
        }

        bsense ^= 1u; grid_barrier(bsense);
        cur = dst;
    }
}

// ---------------------------------------------------------------------------
// Inputs: 0 init_state [4,17,128,128], 1 rand [48,4,1,128,128],
//         2 W1 [128,51], 3 b1 [128], 4 W2 [17,128], 5 b2 [17]
// Output f32: final[:, :4] (262144) then dev_path (48*4*17*128*128).
// ---------------------------------------------------------------------------
extern "C" void kernel_launch(void* const* d_in, const int* in_sizes, int n_in,
                              void* d_out, int out_size)
{
    const float* init_state = (const float*)d_in[0];
    const float* rnd        = (const float*)d_in[1];
    const float* W1         = (const float*)d_in[2];
    const float* b1         = (const float*)d_in[3];
    const float* W2         = (const float*)d_in[4];
    const float* b2         = (const float*)d_in[5];

    float* out      = (float*)d_out;
    float* final_p  = out;
    float* dev_path = out + FINAL_ELEMS;

    cudaFuncSetAttribute(nca_persistent,
                         cudaFuncAttributeMaxDynamicSharedMemorySize, SMEM_BYTES);

    nca_persistent<<<NBLK, 128, SMEM_BYTES>>>(init_state, rnd, W1, b1, W2, b2,
                                              dev_path, final_p);
}

// round 5
// speedup vs baseline: 1.0027x; 1.0027x over previous
#include <cuda_runtime.h>
#include <math.h>

// Problem constants
#define NB    4
#define NC    17
#define NH    128
#define NW    128
#define HWSZ  (NH*NW)
#define NPC   51
#define NWID  128
#define NSTEP 48
#define ALIVE_IDX 3
#define ALIVE_THR 0.1f

#define CHW   (NC*HWSZ)
#define BCHW  (NB*CHW)
#define FINAL_ELEMS (NB*4*HWSZ)
#define NBLK  256

typedef unsigned long long ull;

// f32x2 packed-pair helpers (Blackwell FFMA2 path)
#define F2FMA(d, a, b, c) asm("fma.rn.f32x2 %0, %1, %2, %3;" : "=l"(d) : "l"(a), "l"(b), "l"(c))
#define F2MUL2(d, a, b)   asm("mul.rn.f32x2 %0, %1, %2;"     : "=l"(d) : "l"(a), "l"(b))
#define F2ADD(d, a, b)    asm("add.rn.f32x2 %0, %1, %2;"     : "=l"(d) : "l"(a), "l"(b))
#define PK2(d, lo, hi)    asm("mov.b64 %0, {%1, %2};" : "=l"(d) : "f"(lo), "f"(hi))
#define UPK2(lo, hi, s)   asm("mov.b64 {%0, %1}, %2;" : "=f"(lo), "=f"(hi) : "l"(s))

// Scratch (static device globals; no allocation allowed)
__device__ float         g_alive[NB * HWSZ];       // unmasked new alive channel
__device__ unsigned char g_amask[NB * HWSZ];       // per-pixel alive map (post-mask)
__device__ unsigned      g_count;                  // barrier arrival counter
__device__ volatile unsigned g_sense;              // barrier sense

__device__ __forceinline__ float ldz(const float* __restrict__ ch, int y, int x) {
    if (y < 0 || y >= NH || x < 0 || x >= NW) return 0.0f;
    return __ldg(ch + y * NW + x);
}

// Grid barrier: all NBLK blocks are co-resident by construction (256 blocks,
// 128 thr, occ>=2 on 148 SMs).
__device__ __forceinline__ void grid_barrier(unsigned target) {
    __syncthreads();
    if (threadIdx.x == 0) {
        __threadfence();
        if (atomicAdd(&g_count, 1u) == NBLK - 1u) {
            g_count = 0u;
            __threadfence();
            g_sense = target;
        } else {
            while (g_sense != target) __nanosleep(32);
            __threadfence();
        }
    }
    __syncthreads();
}

// Dynamic smem layout (ull units)
#define S_W1  0
#define S_W2  (128*52)
#define S_B1  (S_W2 + 128*18)
#define S_B2  (S_B1 + 128)
#define SMEM_ULLS (S_B2 + 18)
#define SMEM_BYTES (SMEM_ULLS * 8)

__global__ __launch_bounds__(128, 2)
void nca_persistent(const float* __restrict__ init_state,
                    const float* __restrict__ rnd_all,
                    const float* __restrict__ W1, const float* __restrict__ b1,
                    const float* __restrict__ W2, const float* __restrict__ b2,
                    float* __restrict__ dev_path,   // [48,B,C,H,W]
                    float* __restrict__ final_out)  // [B,4,H,W]
{
    extern __shared__ ull smem[];
    const int tid = threadIdx.x;

    // ---- load duplicated weights once ----
    for (int i = tid; i < 128 * 52; i += 128) {
        int o = i / 52, c = i - o * 52;
        float w = (c < NPC) ? W1[o * NPC + c] : 0.0f;
        ull d; PK2(d, w, w); smem[S_W1 + i] = d;
    }
    for (int i = tid; i < 128 * 18; i += 128) {
        int o = i / 18, j = i - o * 18;
        float w = (j < NC) ? W2[j * NWID + o] : 0.0f;
        ull d; PK2(d, w, w); smem[S_W2 + i] = d;
    }
    { float w = b1[tid]; ull d; PK2(d, w, w); smem[S_B1 + tid] = d; }
    if (tid < 18) { float w = (tid < NC) ? b2[tid] : 0.0f; ull d; PK2(d, w, w); smem[S_B2 + tid] = d; }

    int bias_ok = (b1[tid] <= 0.0f);
    if (tid < NC) bias_ok = bias_ok && (b2[tid] == 0.0f);
    const int allz = __syncthreads_and(bias_ok);

    // ---- geometry: block bid owns spatial region bid (16x4); its 4 warps
    //      handle the 4 batches of that region (load balance: the active blob
    //      is a contiguous bid band -> spread over distinct SMs). ----
    const int bid = blockIdx.x;          // 0..255 = spatial region
    const int rx  = bid & 7;             // region col (16 px wide)
    const int ry  = bid >> 3;            // region row (4 px tall)
    const int b   = tid >> 5;            // warp id = batch
    const int lane = tid & 31;
    const int pr  = lane & 7;            // pair col within region
    const int lyr = lane >> 3;           // row within region (0..3)
    const int bx0 = rx * 16;
    const int x0  = bx0 + pr * 2;
    const int y   = ry * 4 + lyr;
    const int pix = y * NW + x0;

    const ull* w1base = smem + S_W1;
    const ull* w2base = smem + S_W2;
    const ull* b1r    = smem + S_B1;

    unsigned bsense = 0;
    const float* cur = init_state;

    #pragma unroll 1
    for (int t = 0; t < NSTEP; t++) {
        float* dst  = dev_path + (size_t)t * BCHW;
        float* dout = dst + b * CHW + pix;
        float* gal  = g_alive + b * HWSZ + pix;

        // ================= PHASE A: step compute =================
        bool skipped = false;
        if (t > 0 && allz) {
            // check 18x6 alive-map halo of this warp's 16x4 region
            const int hx0 = bx0 - 1, hy0 = ry * 4 - 1;
            unsigned v = 0;
            #pragma unroll
            for (int i = lane; i < 108; i += 32) {
                int hx = hx0 + (i % 18);
                int hy = hy0 + (i / 18);
                if (hx >= 0 && hx < NW && hy >= 0 && hy < NH)
                    v |= __ldcg(&g_amask[b * HWSZ + hy * NW + hx]);
            }
            skipped = !__any_sync(0xFFFFFFFFu, v != 0);
        }

        if (skipped) {
            #pragma unroll
            for (int c = 0; c < NC; c++)
                *reinterpret_cast<ull*>(dout + c * HWSZ) = 0ULL;
            *reinterpret_cast<ull*>(gal) = 0ULL;
        } else {
            // ---- conv loads: 3x4 patch per channel ----
            ull p2[52];
            unsigned nz = 0u;
            const bool interior = (x0 >= 1) && (x0 + 2 < NW) && (y >= 1) && (y + 1 < NH);

            #pragma unroll
            for (int c = 0; c < NC; c++) {
                const float* ch = cur + (b * NC + c) * HWSZ + pix;
                float r0[4], r1[4], r2[4];
                if (interior) {
                    r0[0]=__ldg(ch-NW-1); r0[1]=__ldg(ch-NW); r0[2]=__ldg(ch-NW+1); r0[3]=__ldg(ch-NW+2);
                    r1[0]=__ldg(ch-1);    r1[1]=__ldg(ch);    r1[2]=__ldg(ch+1);    r1[3]=__ldg(ch+2);
                    r2[0]=__ldg(ch+NW-1); r2[1]=__ldg(ch+NW); r2[2]=__ldg(ch+NW+1); r2[3]=__ldg(ch+NW+2);
                } else {
                    const float* chb = cur + (b * NC + c) * HWSZ;
                    r0[0]=ldz(chb,y-1,x0-1); r0[1]=ldz(chb,y-1,x0); r0[2]=ldz(chb,y-1,x0+1); r0[3]=ldz(chb,y-1,x0+2);
                    r1[0]=ldz(chb,y  ,x0-1); r1[1]=ldz(chb,y  ,x0); r1[2]=ldz(chb,y  ,x0+1); r1[3]=ldz(chb,y  ,x0+2);
                    r2[0]=ldz(chb,y+1,x0-1); r2[1]=ldz(chb,y+1,x0); r2[2]=ldz(chb,y+1,x0+1); r2[3]=ldz(chb,y+1,x0+2);
                }
                nz |= __float_as_uint(r0[0]) | __float_as_uint(r0[1]) | __float_as_uint(r0[2]) | __float_as_uint(r0[3]);
                nz |= __float_as_uint(r1[0]) | __float_as_uint(r1[1]) | __float_as_uint(r1[2]) | __float_as_uint(r1[3]);
                nz |= __float_as_uint(r2[0]) | __float_as_uint(r2[1]) | __float_as_uint(r2[2]) | __float_as_uint(r2[3]);

                float gxA = ((r0[2]-r0[0]) + 2.0f*(r1[2]-r1[0]) + (r2[2]-r2[0])) * 0.125f;
                float gxB = ((r0[3]-r0[1]) + 2.0f*(r1[3]-r1[1]) + (r2[3]-r2[1])) * 0.125f;
                float gyA = ((r2[0]-r0[0]) + 2.0f*(r2[1]-r0[1]) + (r2[2]-r0[2])) * 0.125f;
                float gyB = ((r2[1]-r0[1]) + 2.0f*(r2[2]-r0[2]) + (r2[3]-r0[3])) * 0.125f;

                ull d;
                PK2(d, r1[1], r1[2]); p2[c]      = d;
                PK2(d, gxA,   gxB  ); p2[17 + c] = d;
                PK2(d, gyA,   gyB  ); p2[34 + c] = d;
            }
            p2[51] = 0ULL;

            const bool empty = allz && (nz == 0u);
            if (__all_sync(0xFFFFFFFFu, empty)) {
                skipped = true;  // provably zero output; phase B can skip too
                #pragma unroll
                for (int c = 0; c < NC; c++)
                    *reinterpret_cast<ull*>(dout + c * HWSZ) = 0ULL;
                *reinterpret_cast<ull*>(gal) = 0ULL;
            } else {
                // rotation
                {
                    float angA, angB; UPK2(angA, angB, p2[16]);
                    float saA, caA, saB, caB;
                    sincosf(angA, &saA, &caA);
                    sincosf(angB, &saB, &caB);
                    ull ca2, sa2, nsa2;
                    PK2(ca2, caA, caB); PK2(sa2, saA, saB); PK2(nsa2, -saA, -saB);
                    #pragma unroll
                    for (int c = 0; c < NC; c++) {
                        ull gx2 = p2[17 + c], gy2 = p2[34 + c], u;
                        F2MUL2(u, ca2, gx2); F2FMA(u, sa2, gy2, u);  p2[17 + c] = u;
                        F2MUL2(u, ca2, gy2); F2FMA(u, nsa2, gx2, u); p2[34 + c] = u;
                    }
                }

                // MLP
                ull dx2[18];
                #pragma unroll
                for (int j = 0; j < 18; j++) dx2[j] = smem[S_B2 + j];

                const ull* w1r = w1base;
                const ull* w2r = w2base;
                #pragma unroll 2
                for (int o = 0; o < NWID; o++) {
                    ull acc0 = b1r[o];
                    ull acc1 = 0ULL;
                    const ulonglong2* r = reinterpret_cast<const ulonglong2*>(w1r);
                    #pragma unroll
                    for (int q = 0; q < 26; q++) {
                        ulonglong2 wv = r[q];
                        F2FMA(acc0, wv.x, p2[2*q],     acc0);
                        F2FMA(acc1, wv.y, p2[2*q + 1], acc1);
                    }
                    ull hs; F2ADD(hs, acc0, acc1);
                    float hA, hB; UPK2(hA, hB, hs);
                    hA = fmaxf(hA, 0.0f); hB = fmaxf(hB, 0.0f);
                    ull h2; PK2(h2, hA, hB);

                    const ulonglong2* r2 = reinterpret_cast<const ulonglong2*>(w2r);
                    #pragma unroll
                    for (int q = 0; q < 9; q++) {
                        ulonglong2 wv = r2[q];
                        F2FMA(dx2[2*q],     wv.x, h2, dx2[2*q]);
                        F2FMA(dx2[2*q + 1], wv.y, h2, dx2[2*q + 1]);
                    }
                    w1r += 52; w2r += 18;
                }

                // stochastic update
                const float2 rr = *reinterpret_cast<const float2*>(
                    rnd_all + ((size_t)t * NB + b) * HWSZ + pix);
                float mA = (rr.x < 0.5f) ? 1.0f : 0.0f;
                float mB = (rr.y < 0.5f) ? 1.0f : 0.0f;
                ull m2; PK2(m2, mA, mB);

                #pragma unroll
                for (int c = 0; c < NC; c++) {
                    ull nv; F2FMA(nv, dx2[c], m2, p2[c]);
                    *reinterpret_cast<ull*>(dout + c * HWSZ) = nv;
                    if (c == ALIVE_IDX) *reinterpret_cast<ull*>(gal) = nv;
                }
            }
        }

        bsense ^= 1u; grid_barrier(bsense);

        // ================= PHASE B: alive masking =================
        const bool last = (t == NSTEP - 1);

        if (!skipped) {
            // combined 3x4 maxpool patches for the pixel pair
            float mo[4] = {-1e30f,-1e30f,-1e30f,-1e30f};
            float mn[4] = {-1e30f,-1e30f,-1e30f,-1e30f};
            const float* oa = cur + (b * NC + ALIVE_IDX) * HWSZ;
            const unsigned naoff = b * HWSZ;
            #pragma unroll
            for (int dy = -1; dy <= 1; dy++) {
                int yy = y + dy;
                if (yy < 0 || yy >= NH) continue;
                #pragma unroll
                for (int dxx = -1; dxx <= 2; dxx++) {
                    int xx = x0 + dxx;
                    if (xx < 0 || xx >= NW) continue;
                    int idx = yy * NW + xx;
                    float ov = __ldg(oa + idx);
                    float nv = __ldcg(&g_alive[naoff + idx]);
                    mo[dxx + 1] = fmaxf(mo[dxx + 1], ov);
                    mn[dxx + 1] = fmaxf(mn[dxx + 1], nv);
                }
            }
            float moA = fmaxf(fmaxf(mo[0], mo[1]), mo[2]);
            float moB = fmaxf(fmaxf(mo[1], mo[2]), mo[3]);
            float mnA = fmaxf(fmaxf(mn[0], mn[1]), mn[2]);
            float mnB = fmaxf(fmaxf(mn[1], mn[2]), mn[3]);
            const bool aliveA = (moA > ALIVE_THR) && (mnA > ALIVE_THR);
            const bool aliveB = (moB > ALIVE_THR) && (mnB > ALIVE_THR);

            // zero dead pixels (alive pixels already hold correct values)
            if (!aliveA && !aliveB) {
                #pragma unroll
                for (int c = 0; c < NC; c++)
                    *reinterpret_cast<ull*>(dout + c * HWSZ) = 0ULL;
            } else if (!aliveA) {
                #pragma unroll
                for (int c = 0; c < NC; c++) dout[c * HWSZ] = 0.0f;
            } else if (!aliveB) {
                #pragma unroll
                for (int c = 0; c < NC; c++) dout[c * HWSZ + 1] = 0.0f;
            }
            uchar2 am; am.x = aliveA ? 1 : 0; am.y = aliveB ? 1 : 0;
            *reinterpret_cast<uchar2*>(&g_amask[b * HWSZ + pix]) = am;

            if (last) {
                #pragma unroll
                for (int c = 0; c < 4; c++) {
                    float vA = aliveA ? dout[c * HWSZ]     : 0.0f;
                    float vB = aliveB ? dout[c * HWSZ + 1] : 0.0f;
                    float2 fv; fv.x = vA; fv.y = vB;
                    *reinterpret_cast<float2*>(final_out + (b * 4 + c) * HWSZ + pix) = fv;
                }
            }
        } else if (last) {
            #pragma unroll
            for (int c = 0; c < 4; c++)
                *reinterpret_cast<ull*>(final_out + (b * 4 + c) * HWSZ + pix) = 0ULL;
        }

        bsense ^= 1u; grid_barrier(bsense);
        cur = dst;
    }
}

// ---------------------------------------------------------------------------
// Inputs: 0 init_state [4,17,128,128], 1 rand [48,4,1,128,128],
//         2 W1 [128,51], 3 b1 [128], 4 W2 [17,128], 5 b2 [17]
// Output f32: final[:, :4] (262144) then dev_path (48*4*17*128*128).
// ---------------------------------------------------------------------------
extern "C" void kernel_launch(void* const* d_in, const int* in_sizes, int n_in,
                              void* d_out, int out_size)
{
    const float* init_state = (const float*)d_in[0];
    const float* rnd        = (const float*)d_in[1];
    const float* W1         = (const float*)d_in[2];
    const float* b1         = (const float*)d_in[3];
    const float* W2         = (const float*)d_in[4];
    const float* b2         = (const float*)d_in[5];

    float* out      = (float*)d_out;
    float* final_p  = out;
    float* dev_path = out + FINAL_ELEMS;

    cudaFuncSetAttribute(nca_persistent,
                         cudaFuncAttributeMaxDynamicSharedMemorySize, SMEM_BYTES);

    nca_persistent<<<NBLK, 128, SMEM_BYTES>>>(init_state, rnd, W1, b1, W2, b2,
                                              dev_path, final_p);
}

// round 6
// speedup vs baseline: 1.0251x; 1.0224x over previous
#include <cuda_runtime.h>
#include <math.h>

// Problem constants
#define NB    4
#define NC    17
#define NH    128
#define NW    128
#define HWSZ  (NH*NW)
#define NPC   51
#define NWID  128
#define NSTEP 48
#define ALIVE_IDX 3
#define ALIVE_THR 0.1f

#define CHW   (NC*HWSZ)
#define BCHW  (NB*CHW)
#define FINAL_ELEMS (NB*4*HWSZ)
#define NBLK  256

typedef unsigned long long ull;

// f32x2 packed-pair helpers (Blackwell packed fp32 FMA)
#define F2FMA(d, a, b, c) asm("fma.rn.f32x2 %0, %1, %2, %3;" : "=l"(d) : "l"(a), "l"(b), "l"(c))
#define F2MUL2(d, a, b)   asm("mul.rn.f32x2 %0, %1, %2;"     : "=l"(d) : "l"(a), "l"(b))
#define F2ADD(d, a, b)    asm("add.rn.f32x2 %0, %1, %2;"     : "=l"(d) : "l"(a), "l"(b))
#define PK2(d, lo, hi)    asm("mov.b64 %0, {%1, %2};" : "=l"(d) : "f"(lo), "f"(hi))
#define UPK2(lo, hi, s)   asm("mov.b64 {%0, %1}, %2;" : "=f"(lo), "=f"(hi) : "l"(s))

// Static device scratch (no allocation allowed)
__device__ float         g_alive[NB * HWSZ];   // unmasked new alive channel
__device__ unsigned char g_amask[NB * HWSZ];   // per-pixel alive map (post-mask)
__device__ unsigned      g_count;              // barrier arrivals
__device__ volatile unsigned g_sense;          // barrier sense

// Grid barrier over NBLK co-resident blocks (256 blk x 128 thr, occ 2)
__device__ __forceinline__ void grid_barrier(unsigned target) {
    __syncthreads();
    if (threadIdx.x == 0) {
        __threadfence();
        if (atomicAdd(&g_count, 1u) == NBLK - 1u) {
            g_count = 0u;
            __threadfence();
            g_sense = target;
        } else {
            while (g_sense != target) __nanosleep(32);
            __threadfence();
        }
    }
    __syncthreads();
}

// Dynamic smem layout (ull units)
#define S_W1  0
#define S_W2  (128*52)
#define S_B1  (S_W2 + 128*18)
#define S_B2  (S_B1 + 128)
#define SMEM_ULLS (S_B2 + 18)
#define SMEM_BYTES (SMEM_ULLS * 8)

__global__ __launch_bounds__(128, 2)
void nca_persistent(const float* __restrict__ init_state,
                    const float* __restrict__ rnd_all,
                    const float* __restrict__ W1, const float* __restrict__ b1,
                    const float* __restrict__ W2, const float* __restrict__ b2,
                    float* __restrict__ dev_path,   // [48,B,C,H,W] (pre-zeroed)
                    float* __restrict__ final_out)  // [B,4,H,W]   (pre-zeroed)
{
    extern __shared__ ull smem[];
    const int tid = threadIdx.x;

    // ---- load duplicated weights once ----
    for (int i = tid; i < 128 * 52; i += 128) {
        int o = i / 52, c = i - o * 52;
        float w = (c < NPC) ? W1[o * NPC + c] : 0.0f;
        ull d; PK2(d, w, w); smem[S_W1 + i] = d;
    }
    for (int i = tid; i < 128 * 18; i += 128) {
        int o = i / 18, j = i - o * 18;
        float w = (j < NC) ? W2[j * NWID + o] : 0.0f;
        ull d; PK2(d, w, w); smem[S_W2 + i] = d;
    }
    { float w = b1[tid]; ull d; PK2(d, w, w); smem[S_B1 + tid] = d; }
    if (tid < 18) { float w = (tid < NC) ? b2[tid] : 0.0f; ull d; PK2(d, w, w); smem[S_B2 + tid] = d; }

    int bias_ok = (b1[tid] <= 0.0f);
    if (tid < NC) bias_ok = bias_ok && (b2[tid] == 0.0f);
    const int allz = __syncthreads_and(bias_ok);

    // ---- R3 geometry: block = (batch, 16x16 tile); warp = 16x4 row strip ----
    const int bid = blockIdx.x;
    const int b   = bid >> 6;
    const int tle = bid & 63;
    const int bx0 = (tle & 7) * 16;
    const int by0 = (tle >> 3) * 16;

    const int pr  = tid & 7;
    const int lyr = tid >> 3;            // 0..15
    const int x0  = bx0 + pr * 2;
    const int y   = by0 + lyr;
    const int w   = tid >> 5;            // warp 0..3
    const int lane = tid & 31;
    const int sy0 = by0 + 4 * w;         // warp strip top row
    const int pix = y * NW + x0;

    // ---- boundary offsets/masks (reused every step/channel) ----
    const int xm1 = (x0 >= 1) ? x0 - 1 : 0;
    const int xp2 = (x0 + 2 < NW) ? x0 + 2 : NW - 1;
    const int ym1 = (y >= 1) ? y - 1 : 0;
    const int yp1 = (y + 1 < NH) ? y + 1 : NH - 1;
    const int oy0 = ym1 * NW, oy1 = y * NW, oy2 = yp1 * NW;
    const float my0 = (y >= 1) ? 1.0f : 0.0f;
    const float my2 = (y + 1 < NH) ? 1.0f : 0.0f;
    const float mx0 = (x0 >= 1) ? 1.0f : 0.0f;
    const float mx3 = (x0 + 2 < NW) ? 1.0f : 0.0f;
    const float m00 = my0 * mx0, m03 = my0 * mx3;
    const float m20 = my2 * mx0, m23 = my2 * mx3;

    const ull* w1base = smem + S_W1;
    const ull* w2base = smem + S_W2;
    const ull* b1r    = smem + S_B1;

    unsigned bsense = 0;
    const float* cur = init_state;

    #pragma unroll 1
    for (int t = 0; t < NSTEP; t++) {
        float* dst  = dev_path + (size_t)t * BCHW;
        float* dout = dst + b * CHW + pix;
        float* gal  = g_alive + b * HWSZ + pix;

        // ================= PHASE A =================
        bool skipped = false;
        if (t > 0 && allz) {
            // 18x6 alive-map halo of this warp's 16x4 strip
            const int hx0 = bx0 - 1, hy0 = sy0 - 1;
            unsigned v = 0;
            #pragma unroll
            for (int i = lane; i < 108; i += 32) {
                int hx = hx0 + (i % 18);
                int hy = hy0 + (i / 18);
                if (hx >= 0 && hx < NW && hy >= 0 && hy < NH)
                    v |= __ldcg(&g_amask[b * HWSZ + hy * NW + hx]);
            }
            skipped = !__any_sync(0xFFFFFFFFu, v != 0);
        }

        if (skipped) {
            // dev_path slice pre-zeroed; just clear scratch maps
            *reinterpret_cast<ull*>(gal) = 0ULL;
            uchar2 z; z.x = 0; z.y = 0;
            *reinterpret_cast<uchar2*>(&g_amask[b * HWSZ + pix]) = z;
        } else {
            // ---- conv: masked 3x4 patch per channel (single code path) ----
            ull p2[52];
            #pragma unroll
            for (int c = 0; c < NC; c++) {
                const float* ch = cur + (b * NC + c) * HWSZ;
                float a00 = __ldg(ch + oy0 + xm1) * m00;
                float a01 = __ldg(ch + oy0 + x0 ) * my0;
                float a02 = __ldg(ch + oy0 + x0 + 1) * my0;
                float a03 = __ldg(ch + oy0 + xp2) * m03;
                float a10 = __ldg(ch + oy1 + xm1) * mx0;
                float a11 = __ldg(ch + oy1 + x0 );
                float a12 = __ldg(ch + oy1 + x0 + 1);
                float a13 = __ldg(ch + oy1 + xp2) * mx3;
                float a20 = __ldg(ch + oy2 + xm1) * m20;
                float a21 = __ldg(ch + oy2 + x0 ) * my2;
                float a22 = __ldg(ch + oy2 + x0 + 1) * my2;
                float a23 = __ldg(ch + oy2 + xp2) * m23;

                float gxA = ((a02 - a00) + 2.0f * (a12 - a10) + (a22 - a20)) * 0.125f;
                float gxB = ((a03 - a01) + 2.0f * (a13 - a11) + (a23 - a21)) * 0.125f;
                float gyA = ((a20 - a00) + 2.0f * (a21 - a01) + (a22 - a02)) * 0.125f;
                float gyB = ((a21 - a01) + 2.0f * (a22 - a02) + (a23 - a03)) * 0.125f;

                ull d;
                PK2(d, a11, a12); p2[c]      = d;
                PK2(d, gxA, gxB); p2[17 + c] = d;
                PK2(d, gyA, gyB); p2[34 + c] = d;
            }
            p2[51] = 0ULL;

            // ---- rotation ----
            {
                float angA, angB; UPK2(angA, angB, p2[16]);
                float saA, caA, saB, caB;
                sincosf(angA, &saA, &caA);
                sincosf(angB, &saB, &caB);
                ull ca2, sa2, nsa2;
                PK2(ca2, caA, caB); PK2(sa2, saA, saB); PK2(nsa2, -saA, -saB);
                #pragma unroll
                for (int c = 0; c < NC; c++) {
                    ull gx2 = p2[17 + c], gy2 = p2[34 + c], u;
                    F2MUL2(u, ca2, gx2); F2FMA(u, sa2, gy2, u);  p2[17 + c] = u;
                    F2MUL2(u, ca2, gy2); F2FMA(u, nsa2, gx2, u); p2[34 + c] = u;
                }
            }

            // ---- MLP ----
            ull dx2[18];
            #pragma unroll
            for (int j = 0; j < 18; j++) dx2[j] = smem[S_B2 + j];

            const ull* w1r = w1base;
            const ull* w2r = w2base;
            #pragma unroll 1
            for (int o = 0; o < NWID; o++) {
                ull acc0 = b1r[o];
                ull acc1 = 0ULL;
                const ulonglong2* r = reinterpret_cast<const ulonglong2*>(w1r);
                #pragma unroll
                for (int q = 0; q < 26; q++) {
                    ulonglong2 wv = r[q];
                    F2FMA(acc0, wv.x, p2[2*q],     acc0);
                    F2FMA(acc1, wv.y, p2[2*q + 1], acc1);
                }
                ull hs; F2ADD(hs, acc0, acc1);
                float hA, hB; UPK2(hA, hB, hs);
                hA = fmaxf(hA, 0.0f); hB = fmaxf(hB, 0.0f);
                ull h2; PK2(h2, hA, hB);

                const ulonglong2* r2 = reinterpret_cast<const ulonglong2*>(w2r);
                #pragma unroll
                for (int q = 0; q < 9; q++) {
                    ulonglong2 wv = r2[q];
                    F2FMA(dx2[2*q],     wv.x, h2, dx2[2*q]);
                    F2FMA(dx2[2*q + 1], wv.y, h2, dx2[2*q + 1]);
                }
                w1r += 52; w2r += 18;
            }

            // ---- stochastic update ----
            const float2 rr = *reinterpret_cast<const float2*>(
                rnd_all + ((size_t)t * NB + b) * HWSZ + pix);
            float mA = (rr.x < 0.5f) ? 1.0f : 0.0f;
            float mB = (rr.y < 0.5f) ? 1.0f : 0.0f;
            ull m2; PK2(m2, mA, mB);

            #pragma unroll
            for (int c = 0; c < NC; c++) {
                ull nv; F2FMA(nv, dx2[c], m2, p2[c]);
                *reinterpret_cast<ull*>(dout + c * HWSZ) = nv;
                if (c == ALIVE_IDX) *reinterpret_cast<ull*>(gal) = nv;
            }
        }

        bsense ^= 1u; grid_barrier(bsense);

        // ================= PHASE B =================
        const bool last = (t == NSTEP - 1);

        if (!skipped) {
            float mo[4] = {-1e30f,-1e30f,-1e30f,-1e30f};
            float mn[4] = {-1e30f,-1e30f,-1e30f,-1e30f};
            const float* oa = cur + (b * NC + ALIVE_IDX) * HWSZ;
            const unsigned naoff = b * HWSZ;
            #pragma unroll
            for (int dy = -1; dy <= 1; dy++) {
                int yy = y + dy;
                if (yy < 0 || yy >= NH) continue;
                #pragma unroll
                for (int dxx = -1; dxx <= 2; dxx++) {
                    int xx = x0 + dxx;
                    if (xx < 0 || xx >= NW) continue;
                    int idx = yy * NW + xx;
                    float ov = __ldg(oa + idx);
                    float nv = __ldcg(&g_alive[naoff + idx]);
                    mo[dxx + 1] = fmaxf(mo[dxx + 1], ov);
                    mn[dxx + 1] = fmaxf(mn[dxx + 1], nv);
                }
            }
            float moA = fmaxf(fmaxf(mo[0], mo[1]), mo[2]);
            float moB = fmaxf(fmaxf(mo[1], mo[2]), mo[3]);
            float mnA = fmaxf(fmaxf(mn[0], mn[1]), mn[2]);
            float mnB = fmaxf(fmaxf(mn[1], mn[2]), mn[3]);
            const bool aliveA = (moA > ALIVE_THR) && (mnA > ALIVE_THR);
            const bool aliveB = (moB > ALIVE_THR) && (mnB > ALIVE_THR);

            if (!aliveA && !aliveB) {
                #pragma unroll
                for (int c = 0; c < NC; c++)
                    *reinterpret_cast<ull*>(dout + c * HWSZ) = 0ULL;
            } else if (!aliveA) {
                #pragma unroll
                for (int c = 0; c < NC; c++) dout[c * HWSZ] = 0.0f;
            } else if (!aliveB) {
                #pragma unroll
                for (int c = 0; c < NC; c++) dout[c * HWSZ + 1] = 0.0f;
            }
            uchar2 am; am.x = aliveA ? 1 : 0; am.y = aliveB ? 1 : 0;
            *reinterpret_cast<uchar2*>(&g_amask[b * HWSZ + pix]) = am;

            if (last && (aliveA || aliveB)) {
                #pragma unroll
                for (int c = 0; c < 4; c++) {
                    float vA = aliveA ? dout[c * HWSZ]     : 0.0f;
                    float vB = aliveB ? dout[c * HWSZ + 1] : 0.0f;
                    float2 fv; fv.x = vA; fv.y = vB;
                    *reinterpret_cast<float2*>(final_out + (b * 4 + c) * HWSZ + pix) = fv;
                }
            }
        }
        // skipped: outputs pre-zeroed; final_out pre-zeroed.

        bsense ^= 1u; grid_barrier(bsense);
        cur = dst;
    }
}

// ---------------------------------------------------------------------------
// Inputs: 0 init_state [4,17,128,128], 1 rand [48,4,1,128,128],
//         2 W1 [128,51], 3 b1 [128], 4 W2 [17,128], 5 b2 [17]
// Output f32: final[:, :4] (262144) then dev_path (48*4*17*128*128).
// ---------------------------------------------------------------------------
extern "C" void kernel_launch(void* const* d_in, const int* in_sizes, int n_in,
                              void* d_out, int out_size)
{
    const float* init_state = (const float*)d_in[0];
    const float* rnd        = (const float*)d_in[1];
    const float* W1         = (const float*)d_in[2];
    const float* b1         = (const float*)d_in[3];
    const float* W2         = (const float*)d_in[4];
    const float* b2         = (const float*)d_in[5];

    float* out      = (float*)d_out;
    float* final_p  = out;
    float* dev_path = out + FINAL_ELEMS;

    // Pre-zero the whole output once per replay (graph-capturable).
    cudaMemsetAsync(d_out, 0, (size_t)out_size * sizeof(float));

    cudaFuncSetAttribute(nca_persistent,
                         cudaFuncAttributeMaxDynamicSharedMemorySize, SMEM_BYTES);

    nca_persistent<<<NBLK, 128, SMEM_BYTES>>>(init_state, rnd, W1, b1, W2, b2,
                                              dev_path, final_p);
}

// round 7
// speedup vs baseline: 1.5686x; 1.5301x over previous
#include <cuda_runtime.h>
#include <math.h>

// Problem constants
#define NB    4
#define NC    17
#define NH    128
#define NW    128
#define HWSZ  (NH*NW)
#define NPC   51
#define NWID  128
#define NSTEP 48
#define ALIVE_IDX 3
#define ALIVE_THR 0.1f

#define CHW   (NC*HWSZ)
#define BCHW  (NB*CHW)
#define FINAL_ELEMS (NB*4*HWSZ)
#define NBLK  256

typedef unsigned long long ull;

// f32x2 packed-pair helpers
#define F2FMA(d, a, b, c) asm("fma.rn.f32x2 %0, %1, %2, %3;" : "=l"(d) : "l"(a), "l"(b), "l"(c))
#define F2MUL2(d, a, b)   asm("mul.rn.f32x2 %0, %1, %2;"     : "=l"(d) : "l"(a), "l"(b))
#define F2ADD(d, a, b)    asm("add.rn.f32x2 %0, %1, %2;"     : "=l"(d) : "l"(a), "l"(b))
#define PK2(d, lo, hi)    asm("mov.b64 %0, {%1, %2};" : "=l"(d) : "f"(lo), "f"(hi))
#define UPK2(lo, hi, s)   asm("mov.b64 {%0, %1}, %2;" : "=f"(lo), "=f"(hi) : "l"(s))

// Static device scratch
__device__ float         g_alive[NB * HWSZ];   // unmasked new alive channel
__device__ unsigned char g_amask[NB * HWSZ];   // per-pixel alive map (post-mask)
__device__ unsigned      g_count;
__device__ volatile unsigned g_sense;

__device__ __forceinline__ void grid_barrier(unsigned target) {
    __syncthreads();
    if (threadIdx.x == 0) {
        __threadfence();
        if (atomicAdd(&g_count, 1u) == NBLK - 1u) {
            g_count = 0u;
            __threadfence();
            g_sense = target;
        } else {
            while (g_sense != target) __nanosleep(32);
            __threadfence();
        }
    }
    __syncthreads();
}

// Dynamic smem layout (ull units)
#define S_W1  0                      // 128 rows x 52 dup W1
#define S_W2  (S_W1 + 128*52)        // 128 rows x 18 dup W2^T
#define S_B1  (S_W2 + 128*18)        // 128 dup b1
#define S_B2  (S_B1 + 128)           // 18 dup b2
#define S_PB  (S_B2 + 20)            // 32 pairs x 54 p-vector buffer (even idx)
#define PBS   54
#define SMEM_ULLS (S_PB + 32*PBS)
#define SMEM_BYTES (SMEM_ULLS * 8)

__global__ __launch_bounds__(128, 2)
void nca_persistent(const float* __restrict__ init_state,
                    const float* __restrict__ rnd_all,
                    const float* __restrict__ W1, const float* __restrict__ b1,
                    const float* __restrict__ W2, const float* __restrict__ b2,
                    float* __restrict__ dev_path,   // [48,B,C,H,W] (pre-zeroed)
                    float* __restrict__ final_out)  // [B,4,H,W]   (pre-zeroed)
{
    extern __shared__ ull smem[];
    __shared__ int sActive[4];
    const int tid = threadIdx.x;

    // ---- load duplicated weights once ----
    for (int i = tid; i < 128 * 52; i += 128) {
        int o = i / 52, c = i - o * 52;
        float wv = (c < NPC) ? W1[o * NPC + c] : 0.0f;
        ull d; PK2(d, wv, wv); smem[S_W1 + i] = d;
    }
    for (int i = tid; i < 128 * 18; i += 128) {
        int o = i / 18, j = i - o * 18;
        float wv = (j < NC) ? W2[j * NWID + o] : 0.0f;
        ull d; PK2(d, wv, wv); smem[S_W2 + i] = d;
    }
    { float wv = b1[tid]; ull d; PK2(d, wv, wv); smem[S_B1 + tid] = d; }
    if (tid < 18) { float wv = (tid < NC) ? b2[tid] : 0.0f; ull d; PK2(d, wv, wv); smem[S_B2 + tid] = d; }

    int bias_ok = (b1[tid] <= 0.0f);
    if (tid < NC) bias_ok = bias_ok && (b2[tid] == 0.0f);
    const int allz = __syncthreads_and(bias_ok);

    // ---- geometry ----
    const int bid = blockIdx.x;
    const int b   = bid >> 6;
    const int tle = bid & 63;
    const int bx0 = (tle & 7) * 16;
    const int by0 = (tle >> 3) * 16;

    const int w    = tid >> 5;           // warp = strip 0..3
    const int lane = tid & 31;

    // owner-pixel mapping (for skip writes + phase B): 16x16 tile
    const int opr = tid & 7, oly = tid >> 3;
    const int ox0 = bx0 + opr * 2, oy = by0 + oly;
    const int opix = oy * NW + ox0;

    // cooperative mapping: pair 0..31, quad 0..3
    const int mpair = tid >> 2, mq = tid & 3;
    const int mpr = mpair & 7, mply = mpair >> 3;
    const int mx0 = bx0 + mpr * 2;

    // precomputed skip-halo coords (18x6 halo of strip w)
    int hoff[4]; int hval[4];
    {
        const int hx0 = bx0 - 1, hy0 = by0 + 4 * w - 1;
        #pragma unroll
        for (int k = 0; k < 4; k++) {
            int i = lane + 32 * k;
            int hx = hx0 + (i % 18);
            int hy = hy0 + (i / 18);
            hval[k] = (i < 108) && (hx >= 0) && (hx < NW) && (hy >= 0) && (hy < NH);
            hoff[k] = hval[k] ? (b * HWSZ + hy * NW + hx) : 0;
        }
    }

    unsigned bsense = 0;
    const float* cur = init_state;

    #pragma unroll 1
    for (int t = 0; t < NSTEP; t++) {
        float* dst = dev_path + (size_t)t * BCHW;

        // ========== PHASE A1: per-warp skip check ==========
        bool skipped = false;
        if (t > 0 && allz) {
            unsigned v = 0;
            #pragma unroll
            for (int k = 0; k < 4; k++)
                if (hval[k]) v |= __ldcg(&g_amask[hoff[k]]);
            skipped = !__any_sync(0xFFFFFFFFu, v != 0);
        }
        if (lane == 0) sActive[w] = skipped ? 0 : 1;
        if (skipped) {
            *reinterpret_cast<ull*>(&g_alive[b * HWSZ + opix]) = 0ULL;
            uchar2 z; z.x = 0; z.y = 0;
            *reinterpret_cast<uchar2*>(&g_amask[b * HWSZ + opix]) = z;
        }
        __syncthreads();

        // ========== PHASE A2: cooperative dense strips ==========
        #pragma unroll 1
        for (int s = 0; s < 4; s++) {
            if (!sActive[s]) continue;

            const int my   = by0 + s * 4 + mply;
            const int mpix = my * NW + mx0;
            ull* pb = smem + S_PB + mpair * PBS;

            // --- cooperative conv: 4 threads/pair, channels mq,mq+4,... ---
            {
                const int xm1 = (mx0 >= 1) ? mx0 - 1 : 0;
                const int xp2 = (mx0 + 2 < NW) ? mx0 + 2 : NW - 1;
                const int ym1 = (my >= 1) ? my - 1 : 0;
                const int yp1 = (my + 1 < NH) ? my + 1 : NH - 1;
                const int oy0 = ym1 * NW, oy1 = my * NW, oy2 = yp1 * NW;
                const float fy0 = (my >= 1) ? 1.0f : 0.0f;
                const float fy2 = (my + 1 < NH) ? 1.0f : 0.0f;
                const float fx0 = (mx0 >= 1) ? 1.0f : 0.0f;
                const float fx3 = (mx0 + 2 < NW) ? 1.0f : 0.0f;
                const float m00 = fy0 * fx0, m03 = fy0 * fx3;
                const float m20 = fy2 * fx0, m23 = fy2 * fx3;

                for (int c = mq; c < NC; c += 4) {
                    const float* ch = cur + (b * NC + c) * HWSZ;
                    float a00 = __ldg(ch + oy0 + xm1) * m00;
                    float a01 = __ldg(ch + oy0 + mx0) * fy0;
                    float a02 = __ldg(ch + oy0 + mx0 + 1) * fy0;
                    float a03 = __ldg(ch + oy0 + xp2) * m03;
                    float a10 = __ldg(ch + oy1 + xm1) * fx0;
                    float a11 = __ldg(ch + oy1 + mx0);
                    float a12 = __ldg(ch + oy1 + mx0 + 1);
                    float a13 = __ldg(ch + oy1 + xp2) * fx3;
                    float a20 = __ldg(ch + oy2 + xm1) * m20;
                    float a21 = __ldg(ch + oy2 + mx0) * fy2;
                    float a22 = __ldg(ch + oy2 + mx0 + 1) * fy2;
                    float a23 = __ldg(ch + oy2 + xp2) * m23;

                    float gxA = ((a02 - a00) + 2.0f * (a12 - a10) + (a22 - a20)) * 0.125f;
                    float gxB = ((a03 - a01) + 2.0f * (a13 - a11) + (a23 - a21)) * 0.125f;
                    float gyA = ((a20 - a00) + 2.0f * (a21 - a01) + (a22 - a02)) * 0.125f;
                    float gyB = ((a21 - a01) + 2.0f * (a22 - a02) + (a23 - a03)) * 0.125f;

                    ull d;
                    PK2(d, a11, a12); pb[c] = d;
                    PK2(d, gxA, gxB); pb[17 + c] = d;
                    PK2(d, gyA, gyB); pb[34 + c] = d;

                    if (c == 16) {
                        float saA, caA, saB, caB;
                        sincosf(a11, &saA, &caA);
                        sincosf(a12, &saB, &caB);
                        ull ca2, sa2;
                        PK2(ca2, caA, caB); PK2(sa2, saA, saB);
                        pb[51] = 0ULL; pb[52] = ca2; pb[53] = sa2;
                    }
                }
            }
            __syncthreads();

            // --- cooperative MLP: thread (pair, quad), o = 4*i + quad ---
            {
                ull p2[52];
                const ulonglong2* pbr = reinterpret_cast<const ulonglong2*>(pb);
                #pragma unroll
                for (int q = 0; q < 26; q++) {
                    ulonglong2 v = pbr[q];
                    p2[2 * q] = v.x; p2[2 * q + 1] = v.y;
                }
                // rotation
                {
                    ull ca2 = pb[52], sa2 = pb[53];
                    float sA, sB; UPK2(sA, sB, sa2);
                    ull nsa2; PK2(nsa2, -sA, -sB);
                    #pragma unroll
                    for (int c = 0; c < NC; c++) {
                        ull gx2 = p2[17 + c], gy2 = p2[34 + c], u;
                        F2MUL2(u, ca2, gx2); F2FMA(u, sa2, gy2, u);  p2[17 + c] = u;
                        F2MUL2(u, ca2, gy2); F2FMA(u, nsa2, gx2, u); p2[34 + c] = u;
                    }
                }

                ull dx2[18];
                #pragma unroll
                for (int j = 0; j < 18; j++)
                    dx2[j] = (mq == 0) ? smem[S_B2 + j] : 0ULL;

                #pragma unroll 1
                for (int i = 0; i < 32; i++) {
                    const int o = 4 * i + mq;
                    ull acc0 = smem[S_B1 + o];
                    ull acc1 = 0ULL, acc2 = 0ULL, acc3 = 0ULL;
                    const ulonglong2* r = reinterpret_cast<const ulonglong2*>(smem + S_W1 + o * 52);
                    #pragma unroll
                    for (int q = 0; q < 13; q++) {
                        ulonglong2 wv = r[q];
                        ulonglong2 wu = r[q + 13];
                        F2FMA(acc0, wv.x, p2[2 * q],      acc0);
                        F2FMA(acc1, wv.y, p2[2 * q + 1],  acc1);
                        F2FMA(acc2, wu.x, p2[2 * q + 26], acc2);
                        F2FMA(acc3, wu.y, p2[2 * q + 27], acc3);
                    }
                    ull s02, s13, hs;
                    F2ADD(s02, acc0, acc2); F2ADD(s13, acc1, acc3); F2ADD(hs, s02, s13);
                    float hA, hB; UPK2(hA, hB, hs);
                    hA = fmaxf(hA, 0.0f); hB = fmaxf(hB, 0.0f);
                    ull h2; PK2(h2, hA, hB);

                    const ulonglong2* r2 = reinterpret_cast<const ulonglong2*>(smem + S_W2 + o * 18);
                    #pragma unroll
                    for (int q = 0; q < 9; q++) {
                        ulonglong2 wv = r2[q];
                        F2FMA(dx2[2 * q],     wv.x, h2, dx2[2 * q]);
                        F2FMA(dx2[2 * q + 1], wv.y, h2, dx2[2 * q + 1]);
                    }
                }

                // quad reduction (width 4)
                #pragma unroll
                for (int j = 0; j < 18; j++) {
                    ull o2 = __shfl_down_sync(0xFFFFFFFFu, dx2[j], 2, 4);
                    F2ADD(dx2[j], dx2[j], o2);
                    o2 = __shfl_down_sync(0xFFFFFFFFu, dx2[j], 1, 4);
                    F2ADD(dx2[j], dx2[j], o2);
                }

                if (mq == 0) {
                    const float2 rr = *reinterpret_cast<const float2*>(
                        rnd_all + ((size_t)t * NB + b) * HWSZ + mpix);
                    float mA = (rr.x < 0.5f) ? 1.0f : 0.0f;
                    float mB = (rr.y < 0.5f) ? 1.0f : 0.0f;
                    ull m2; PK2(m2, mA, mB);
                    float* dout = dst + b * CHW + mpix;
                    #pragma unroll
                    for (int c = 0; c < NC; c++) {
                        ull nv; F2FMA(nv, dx2[c], m2, p2[c]);
                        *reinterpret_cast<ull*>(dout + c * HWSZ) = nv;
                        if (c == ALIVE_IDX)
                            *reinterpret_cast<ull*>(&g_alive[b * HWSZ + mpix]) = nv;
                    }
                }
            }
            __syncthreads();
        }

        bsense ^= 1u; grid_barrier(bsense);

        // ========== PHASE B: alive masking (owner mapping) ==========
        const bool last = (t == NSTEP - 1);
        if (sActive[w]) {
            float* dout = dst + b * CHW + opix;
            float mo[4] = {-1e30f, -1e30f, -1e30f, -1e30f};
            float mn[4] = {-1e30f, -1e30f, -1e30f, -1e30f};
            const float* oa = cur + (b * NC + ALIVE_IDX) * HWSZ;
            const unsigned naoff = b * HWSZ;
            #pragma unroll
            for (int dy = -1; dy <= 1; dy++) {
                int yy = oy + dy;
                if (yy < 0 || yy >= NH) continue;
                #pragma unroll
                for (int dxx = -1; dxx <= 2; dxx++) {
                    int xx = ox0 + dxx;
                    if (xx < 0 || xx >= NW) continue;
                    int idx = yy * NW + xx;
                    float ov = __ldg(oa + idx);
                    float nv = __ldcg(&g_alive[naoff + idx]);
                    mo[dxx + 1] = fmaxf(mo[dxx + 1], ov);
                    mn[dxx + 1] = fmaxf(mn[dxx + 1], nv);
                }
            }
            float moA = fmaxf(fmaxf(mo[0], mo[1]), mo[2]);
            float moB = fmaxf(fmaxf(mo[1], mo[2]), mo[3]);
            float mnA = fmaxf(fmaxf(mn[0], mn[1]), mn[2]);
            float mnB = fmaxf(fmaxf(mn[1], mn[2]), mn[3]);
            const bool aliveA = (moA > ALIVE_THR) && (mnA > ALIVE_THR);
            const bool aliveB = (moB > ALIVE_THR) && (mnB > ALIVE_THR);

            if (!aliveA && !aliveB) {
                #pragma unroll
                for (int c = 0; c < NC; c++)
                    *reinterpret_cast<ull*>(dout + c * HWSZ) = 0ULL;
            } else if (!aliveA) {
                #pragma unroll
                for (int c = 0; c < NC; c++) dout[c * HWSZ] = 0.0f;
            } else if (!aliveB) {
                #pragma unroll
                for (int c = 0; c < NC; c++) dout[c * HWSZ + 1] = 0.0f;
            }
            uchar2 am; am.x = aliveA ? 1 : 0; am.y = aliveB ? 1 : 0;
            *reinterpret_cast<uchar2*>(&g_amask[b * HWSZ + opix]) = am;

            if (last && (aliveA || aliveB)) {
                #pragma unroll
                for (int c = 0; c < 4; c++) {
                    float vA = aliveA ? dout[c * HWSZ]     : 0.0f;
                    float vB = aliveB ? dout[c * HWSZ + 1] : 0.0f;
                    float2 fv; fv.x = vA; fv.y = vB;
                    *reinterpret_cast<float2*>(final_out + (b * 4 + c) * HWSZ + opix) = fv;
                }
            }
        }

        bsense ^= 1u; grid_barrier(bsense);
        cur = dst;
    }
}

// ---------------------------------------------------------------------------
// Inputs: 0 init_state [4,17,128,128], 1 rand [48,4,1,128,128],
//         2 W1 [128,51], 3 b1 [128], 4 W2 [17,128], 5 b2 [17]
// Output f32: final[:, :4] (262144) then dev_path (48*4*17*128*128).
// ---------------------------------------------------------------------------
extern "C" void kernel_launch(void* const* d_in, const int* in_sizes, int n_in,
                              void* d_out, int out_size)
{
    const float* init_state = (const float*)d_in[0];
    const float* rnd        = (const float*)d_in[1];
    const float* W1         = (const float*)d_in[2];
    const float* b1         = (const float*)d_in[3];
    const float* W2         = (const float*)d_in[4];
    const float* b2         = (const float*)d_in[5];

    float* out      = (float*)d_out;
    float* final_p  = out;
    float* dev_path = out + FINAL_ELEMS;

    cudaMemsetAsync(d_out, 0, (size_t)out_size * sizeof(float));

    cudaFuncSetAttribute(nca_persistent,
                         cudaFuncAttributeMaxDynamicSharedMemorySize, SMEM_BYTES);

    nca_persistent<<<NBLK, 128, SMEM_BYTES>>>(init_state, rnd, W1, b1, W2, b2,
                                              dev_path, final_p);
}